// round 10
// baseline (speedup 1.0000x reference)
#include <cuda_runtime.h>
#include <cuda_bf16.h>
#include <cuda_fp16.h>
#include <cstdint>

#define N_NODES 100000
#define N_EDGES 1600000
#define DH 128
#define NGRAPH 128
#define NB ((N_NODES + 255) / 256)   // scan blocks

// ---------------- device scratch ----------------
__device__ int   g_cnt[N_NODES];
__device__ float g_dinv[N_NODES];
__device__ float g_dinv2[N_NODES];
__device__ int   g_rowptr[N_NODES + 1];
__device__ int   g_cur[N_NODES];
__device__ int   g_bsum[NB];
__device__ int   g_boff[NB];
__device__ int   g_csr_src[N_EDGES];
__device__ float g_csr_w[N_EDGES];
__device__ float g_h[(size_t)N_NODES * DH];      // fp32 (written only by last layer; pool reads)
__device__ __half g_hf16[(size_t)N_NODES * DH];  // fp16 activations for gather
__device__ __half g_xf16[(size_t)N_NODES * DH];  // fp16 copy of input x
__device__ float g_agg[(size_t)N_NODES * DH];

// ---------------- prep ----------------
__global__ void k_zero() {
    int i = blockIdx.x * blockDim.x + threadIdx.x;
    if (i < N_NODES) g_cnt[i] = 0;
}
__global__ void k_deg(const int* __restrict__ ei) {
    int e = blockIdx.x * blockDim.x + threadIdx.x;
    if (e >= N_EDGES) return;
    atomicAdd(&g_cnt[ei[N_EDGES + e]], 1);
}
__global__ void k_dinv() {
    int i = blockIdx.x * blockDim.x + threadIdx.x;
    if (i >= N_NODES) return;
    float d = rsqrtf((float)(g_cnt[i] + 1));
    g_dinv[i] = d;
    g_dinv2[i] = d * d;
}
__global__ void k_scan1() {
    __shared__ int sh[256];
    int i = blockIdx.x * 256 + threadIdx.x;
    sh[threadIdx.x] = (i < N_NODES) ? g_cnt[i] : 0;
    __syncthreads();
#pragma unroll
    for (int s = 128; s > 0; s >>= 1) {
        if (threadIdx.x < s) sh[threadIdx.x] += sh[threadIdx.x + s];
        __syncthreads();
    }
    if (threadIdx.x == 0) g_bsum[blockIdx.x] = sh[0];
}
__global__ void k_scan2() {
    __shared__ int sh[512];
    int t = threadIdx.x;
    sh[t] = (t < NB) ? g_bsum[t] : 0;
    __syncthreads();
#pragma unroll
    for (int d = 1; d < 512; d <<= 1) {
        int v = (t >= d) ? sh[t - d] : 0;
        __syncthreads();
        sh[t] += v;
        __syncthreads();
    }
    if (t < NB) g_boff[t] = sh[t] - g_bsum[t];
    if (t == 0) g_rowptr[N_NODES] = N_EDGES;
}
__global__ void k_scan3() {
    __shared__ int sh[256];
    int t = threadIdx.x;
    int i = blockIdx.x * 256 + t;
    int v = (i < N_NODES) ? g_cnt[i] : 0;
    sh[t] = v;
    __syncthreads();
#pragma unroll
    for (int d = 1; d < 256; d <<= 1) {
        int u = (t >= d) ? sh[t - d] : 0;
        __syncthreads();
        sh[t] += u;
        __syncthreads();
    }
    if (i < N_NODES) {
        int excl = g_boff[blockIdx.x] + sh[t] - v;
        g_rowptr[i] = excl;
        g_cur[i] = excl;
    }
}
__global__ void k_fill(const int* __restrict__ ei) {
    int e = blockIdx.x * blockDim.x + threadIdx.x;
    if (e >= N_EDGES) return;
    int r = ei[e];
    int c = ei[N_EDGES + e];
    int pos = atomicAdd(&g_cur[c], 1);
    g_csr_src[pos] = r;
    g_csr_w[pos] = g_dinv[r] * g_dinv[c];
}

// convert x fp32 -> fp16
__global__ void k_xf16(const float* __restrict__ x) {
    int t = blockIdx.x * blockDim.x + threadIdx.x;
    if (t >= N_NODES * (DH / 4)) return;
    float4 v = ((const float4*)x)[t];
    __half2 h0 = __floats2half2_rn(v.x, v.y);
    __half2 h1 = __floats2half2_rn(v.z, v.w);
    uint2 u;
    u.x = *(uint32_t*)&h0;
    u.y = *(uint32_t*)&h1;
    ((uint2*)g_xf16)[t] = u;
}

// ---------------- pull gather (fp16 source, fp32 accumulate) ----------------
__device__ __forceinline__ float4 ld_row4(const __half* __restrict__ src,
                                          int node, int lane4) {
    uint2 u = *(const uint2*)&src[(size_t)node * DH + lane4];
    __half2 p0 = *(__half2*)&u.x;
    __half2 p1 = *(__half2*)&u.y;
    float2 f0 = __half22float2(p0);
    float2 f1 = __half22float2(p1);
    return make_float4(f0.x, f0.y, f1.x, f1.y);
}

// one warp per node; indices/weights fetched coalesced (lane-per-edge) then shuffled
__device__ __forceinline__ void gather_body(const __half* __restrict__ src) {
    int w = (blockIdx.x * blockDim.x + threadIdx.x) >> 5;
    if (w >= N_NODES) return;
    int lane = threadIdx.x & 31;
    int lane4 = lane * 4;
    int s = g_rowptr[w];
    int e = g_rowptr[w + 1];
    float d2 = g_dinv2[w];
    float4 v0 = ld_row4(src, w, lane4);
    float4 acc0 = make_float4(v0.x * d2, v0.y * d2, v0.z * d2, v0.w * d2);
    float4 acc1 = make_float4(0.f, 0.f, 0.f, 0.f);

    for (int base = s; base < e; base += 32) {
        int cnt = e - base;
        if (cnt > 32) cnt = 32;
        int idx = 0;
        float wt = 0.f;
        if (lane < cnt) {
            idx = g_csr_src[base + lane];
            wt = g_csr_w[base + lane];
        }
        int j = 0;
        for (; j + 4 <= cnt; j += 4) {
            int r0 = __shfl_sync(0xffffffffu, idx, j);
            int r1 = __shfl_sync(0xffffffffu, idx, j + 1);
            int r2 = __shfl_sync(0xffffffffu, idx, j + 2);
            int r3 = __shfl_sync(0xffffffffu, idx, j + 3);
            float w0 = __shfl_sync(0xffffffffu, wt, j);
            float w1 = __shfl_sync(0xffffffffu, wt, j + 1);
            float w2 = __shfl_sync(0xffffffffu, wt, j + 2);
            float w3 = __shfl_sync(0xffffffffu, wt, j + 3);
            float4 a = ld_row4(src, r0, lane4);
            float4 b = ld_row4(src, r1, lane4);
            float4 c = ld_row4(src, r2, lane4);
            float4 d = ld_row4(src, r3, lane4);
            acc0.x += a.x * w0 + b.x * w1;
            acc0.y += a.y * w0 + b.y * w1;
            acc0.z += a.z * w0 + b.z * w1;
            acc0.w += a.w * w0 + b.w * w1;
            acc1.x += c.x * w2 + d.x * w3;
            acc1.y += c.y * w2 + d.y * w3;
            acc1.z += c.z * w2 + d.z * w3;
            acc1.w += c.w * w2 + d.w * w3;
        }
        for (; j < cnt; j++) {
            int r0 = __shfl_sync(0xffffffffu, idx, j);
            float w0 = __shfl_sync(0xffffffffu, wt, j);
            float4 a = ld_row4(src, r0, lane4);
            acc0.x += a.x * w0; acc0.y += a.y * w0;
            acc0.z += a.z * w0; acc0.w += a.w * w0;
        }
    }
    acc0.x += acc1.x; acc0.y += acc1.y; acc0.z += acc1.z; acc0.w += acc1.w;
    *(float4*)&g_agg[(size_t)w * DH + lane4] = acc0;
}
__global__ void k_gather_x16() { gather_body(g_xf16); }
__global__ void k_gather_h16() { gather_body(g_hf16); }

// ================= HMMA GEMM: h = tanh(agg @ W + b) =================
#define TSTRIDE 136            // bf16 elems per row (+8 pad)
#define TILE_BYTES (128 * TSTRIDE * 2)   // 34816
#define OFF_AH 0
#define OFF_AL (OFF_AH + TILE_BYTES)
#define OFF_BH (OFF_AL + TILE_BYTES)
#define OFF_BL (OFF_BH + TILE_BYTES)
#define GEMM_SMEM (4 * TILE_BYTES)       // 139264 bytes

__device__ __forceinline__ void split_store8(char* sm_hi, char* sm_lo,
                                             int row, int k, const float* v) {
    uint32_t hw[4], lw[4];
#pragma unroll
    for (int i = 0; i < 4; i++) {
        __nv_bfloat16 h0 = __float2bfloat16(v[2 * i]);
        __nv_bfloat16 h1 = __float2bfloat16(v[2 * i + 1]);
        float r0 = v[2 * i] - __bfloat162float(h0);
        float r1 = v[2 * i + 1] - __bfloat162float(h1);
        __nv_bfloat16 l0 = __float2bfloat16(r0);
        __nv_bfloat16 l1 = __float2bfloat16(r1);
        hw[i] = (uint32_t)__bfloat16_as_ushort(h0) | ((uint32_t)__bfloat16_as_ushort(h1) << 16);
        lw[i] = (uint32_t)__bfloat16_as_ushort(l0) | ((uint32_t)__bfloat16_as_ushort(l1) << 16);
    }
    uint32_t o = (uint32_t)row * (TSTRIDE * 2) + (uint32_t)k * 2;
    *(uint4*)(sm_hi + o) = make_uint4(hw[0], hw[1], hw[2], hw[3]);
    *(uint4*)(sm_lo + o) = make_uint4(lw[0], lw[1], lw[2], lw[3]);
}

__device__ __forceinline__ void mma_bf16(float* c, uint32_t a0, uint32_t a1,
                                         uint32_t a2, uint32_t a3,
                                         uint32_t b0, uint32_t b1) {
    asm volatile(
        "mma.sync.aligned.m16n8k16.row.col.f32.bf16.bf16.f32 "
        "{%0,%1,%2,%3}, {%4,%5,%6,%7}, {%8,%9}, {%0,%1,%2,%3};"
        : "+f"(c[0]), "+f"(c[1]), "+f"(c[2]), "+f"(c[3])
        : "r"(a0), "r"(a1), "r"(a2), "r"(a3), "r"(b0), "r"(b1));
}

// outMode: 0 -> write fp16 only (hidden layers); 1 -> write fp32 only (last layer)
__global__ void __launch_bounds__(256) k_gemm_mma(const float* __restrict__ W,
                                                  const float* __restrict__ bv,
                                                  int outMode) {
    extern __shared__ char smem[];
    int tid = threadIdx.x;
    int wid = tid >> 5;
    int lane = tid & 31;
    int rowBase = blockIdx.x * 128;

    // ---- stage A (agg) -> sAh/sAl
    {
        int r = tid >> 1;
        int kbase = (tid & 1) * 64;
        int gr = rowBase + r;
        bool valid = gr < N_NODES;
        const float* arow = &g_agg[(size_t)gr * DH];
#pragma unroll
        for (int kc = 0; kc < 64; kc += 8) {
            int k = kbase + kc;
            float v[8];
            if (valid) {
                float4 p = *(const float4*)&arow[k];
                float4 q = *(const float4*)&arow[k + 4];
                v[0] = p.x; v[1] = p.y; v[2] = p.z; v[3] = p.w;
                v[4] = q.x; v[5] = q.y; v[6] = q.z; v[7] = q.w;
            } else {
#pragma unroll
                for (int i = 0; i < 8; i++) v[i] = 0.f;
            }
            split_store8(smem + OFF_AH, smem + OFF_AL, r, k, v);
        }
    }
    // ---- stage B = W^T -> sBh/sBl  (sB[n][k] = W[k][n])
    {
        int n = tid & 127;
        int kh = (tid >> 7) * 64;
#pragma unroll
        for (int kc = 0; kc < 64; kc += 8) {
            int k = kh + kc;
            float v[8];
#pragma unroll
            for (int i = 0; i < 8; i++) v[i] = __ldg(&W[(size_t)(k + i) * DH + n]);
            split_store8(smem + OFF_BH, smem + OFF_BL, n, k, v);
        }
    }
    __syncthreads();

    // ---- compute: warp wid owns rows [wid*16, wid*16+16), all 128 cols
    int g = lane >> 2;
    int tq = lane & 3;
    float acc[16][4];
#pragma unroll
    for (int nt = 0; nt < 16; nt++) {
        acc[nt][0] = acc[nt][1] = acc[nt][2] = acc[nt][3] = 0.f;
    }

    uint32_t aoff0 = (uint32_t)(wid * 16 + g) * (TSTRIDE * 2) + tq * 4;
    uint32_t aoff1 = aoff0 + 8 * (TSTRIDE * 2);
    uint32_t boffBase = (uint32_t)g * (TSTRIDE * 2) + tq * 4;

#pragma unroll
    for (int pass = 0; pass < 3; pass++) {
        const char* pA = smem + ((pass == 2) ? OFF_AL : OFF_AH);
        const char* pB = smem + ((pass == 1) ? OFF_BL : OFF_BH);
#pragma unroll
        for (int ks = 0; ks < 8; ks++) {
            uint32_t ko = (uint32_t)ks * 32;
            uint32_t a0 = *(const uint32_t*)(pA + aoff0 + ko);
            uint32_t a2 = *(const uint32_t*)(pA + aoff0 + ko + 16);
            uint32_t a1 = *(const uint32_t*)(pA + aoff1 + ko);
            uint32_t a3 = *(const uint32_t*)(pA + aoff1 + ko + 16);
#pragma unroll
            for (int nt = 0; nt < 16; nt++) {
                uint32_t bo = boffBase + (uint32_t)nt * 8 * (TSTRIDE * 2) + ko;
                uint32_t b0 = *(const uint32_t*)(pB + bo);
                uint32_t b1 = *(const uint32_t*)(pB + bo + 16);
                mma_bf16(acc[nt], a0, a1, a2, a3, b0, b1);
            }
        }
    }

    // ---- epilogue: bias + tanh
    int row0 = rowBase + wid * 16 + g;
    int row1 = row0 + 8;
#pragma unroll
    for (int nt = 0; nt < 16; nt++) {
        int col = nt * 8 + tq * 2;
        float bx = __ldg(&bv[col]);
        float by = __ldg(&bv[col + 1]);
        if (row0 < N_NODES) {
            float ox = tanhf(acc[nt][0] + bx);
            float oy = tanhf(acc[nt][1] + by);
            if (outMode == 0) {
                *(__half2*)&g_hf16[(size_t)row0 * DH + col] = __floats2half2_rn(ox, oy);
            } else {
                *(float2*)&g_h[(size_t)row0 * DH + col] = make_float2(ox, oy);
            }
        }
        if (row1 < N_NODES) {
            float ox = tanhf(acc[nt][2] + bx);
            float oy = tanhf(acc[nt][3] + by);
            if (outMode == 0) {
                *(__half2*)&g_hf16[(size_t)row1 * DH + col] = __floats2half2_rn(ox, oy);
            } else {
                *(float2*)&g_h[(size_t)row1 * DH + col] = make_float2(ox, oy);
            }
        }
    }
}

// ---------------- pooling + linear head ----------------
__device__ __forceinline__ int lb_search(const int* b, int n, int v) {
    int lo = 0, hi = n;
    while (lo < hi) {
        int m = (lo + hi) >> 1;
        if (b[m] < v) lo = m + 1; else hi = m;
    }
    return lo;
}

__global__ void k_pool(const int* __restrict__ batch,
                       const float* __restrict__ Wl,
                       const float* __restrict__ bl,
                       float* __restrict__ out) {
    int g = blockIdx.x;
    int tid = threadIdx.x;
    int start = lb_search(batch, N_NODES, g);
    int end   = lb_search(batch, N_NODES, g + 1);
    float mx = -3.402823466e+38f;
    float sm = 0.f;
    for (int n = start; n < end; n++) {
        float v = g_h[(size_t)n * DH + tid];
        mx = fmaxf(mx, v);
        sm += v;
    }
    int cnt = end - start;
    float mn;
    if (cnt > 0) {
        mn = sm / (float)cnt;
    } else {
        mx = 0.f;
        mn = 0.f;
    }
    float contrib = mx * Wl[tid] + mn * Wl[DH + tid];
    __shared__ float red[128];
    red[tid] = contrib;
    __syncthreads();
#pragma unroll
    for (int s = 64; s > 0; s >>= 1) {
        if (tid < s) red[tid] += red[tid + s];
        __syncthreads();
    }
    if (tid == 0) out[g] = red[0] + bl[0];
}

// ---------------- launch ----------------
extern "C" void kernel_launch(void* const* d_in, const int* in_sizes, int n_in,
                              void* d_out, int out_size) {
    const float* x     = (const float*)d_in[0];
    const int*   ei    = (const int*)d_in[1];
    const int*   batch = (const int*)d_in[2];
    const float* W1 = (const float*)d_in[3];
    const float* b1 = (const float*)d_in[4];
    const float* W2 = (const float*)d_in[5];
    const float* b2 = (const float*)d_in[6];
    const float* W3 = (const float*)d_in[7];
    const float* b3 = (const float*)d_in[8];
    const float* W4 = (const float*)d_in[9];
    const float* b4 = (const float*)d_in[10];
    const float* Wl = (const float*)d_in[11];
    const float* bl = (const float*)d_in[12];
    float* out = (float*)d_out;

    cudaFuncSetAttribute(k_gemm_mma, cudaFuncAttributeMaxDynamicSharedMemorySize, GEMM_SMEM);

    const int T = 256;
    k_zero<<<(N_NODES + T - 1) / T, T>>>();
    k_deg<<<(N_EDGES + T - 1) / T, T>>>(ei);
    k_dinv<<<(N_NODES + T - 1) / T, T>>>();
    k_scan1<<<NB, 256>>>();
    k_scan2<<<1, 512>>>();
    k_scan3<<<NB, 256>>>();
    k_fill<<<(N_EDGES + T - 1) / T, T>>>(ei);
    k_xf16<<<(N_NODES * (DH / 4) + T - 1) / T, T>>>(x);

    const int gatherBlocks = (N_NODES * 32 + T - 1) / T;
    const int gemmBlocks = (N_NODES + 127) / 128;

    k_gather_x16<<<gatherBlocks, T>>>();
    k_gemm_mma<<<gemmBlocks, 256, GEMM_SMEM>>>(W1, b1, 0);
    k_gather_h16<<<gatherBlocks, T>>>();
    k_gemm_mma<<<gemmBlocks, 256, GEMM_SMEM>>>(W2, b2, 0);
    k_gather_h16<<<gatherBlocks, T>>>();
    k_gemm_mma<<<gemmBlocks, 256, GEMM_SMEM>>>(W3, b3, 0);
    k_gather_h16<<<gatherBlocks, T>>>();
    k_gemm_mma<<<gemmBlocks, 256, GEMM_SMEM>>>(W4, b4, 1);

    k_pool<<<NGRAPH, 128>>>(batch, Wl, bl, out);
}

// round 11
// speedup vs baseline: 1.0255x; 1.0255x over previous
#include <cuda_runtime.h>
#include <cuda_bf16.h>
#include <cuda_fp16.h>
#include <cstdint>

#define N_NODES 100000
#define N_EDGES 1600000
#define DH 128
#define NGRAPH 128
#define NB ((N_NODES + 255) / 256)   // scan blocks

// ---------------- device scratch ----------------
__device__ int   g_cnt[N_NODES];
__device__ float g_dinv[N_NODES];
__device__ float g_dinv2[N_NODES];
__device__ int   g_rowptr[N_NODES + 1];
__device__ int   g_cur[N_NODES];
__device__ int   g_bsum[NB];
__device__ int   g_boff[NB];
__device__ int   g_csr_src[N_EDGES];
__device__ float g_csr_w[N_EDGES];
__device__ float g_h[(size_t)N_NODES * DH];      // fp32 (last layer only; pool reads)
__device__ __half g_hf16[(size_t)N_NODES * DH];  // fp16 activations for gather
__device__ __half g_xf16[(size_t)N_NODES * DH];  // fp16 copy of input x
__device__ float g_agg[(size_t)N_NODES * DH];

// ---------------- prep ----------------
__global__ void k_zero() {
    int i = blockIdx.x * blockDim.x + threadIdx.x;
    if (i < N_NODES) g_cnt[i] = 0;
}
__global__ void k_deg(const int* __restrict__ ei) {
    int e = blockIdx.x * blockDim.x + threadIdx.x;
    if (e >= N_EDGES) return;
    atomicAdd(&g_cnt[ei[N_EDGES + e]], 1);
}
__global__ void k_dinv() {
    int i = blockIdx.x * blockDim.x + threadIdx.x;
    if (i >= N_NODES) return;
    float d = rsqrtf((float)(g_cnt[i] + 1));
    g_dinv[i] = d;
    g_dinv2[i] = d * d;
}
__global__ void k_scan1() {
    __shared__ int sh[256];
    int i = blockIdx.x * 256 + threadIdx.x;
    sh[threadIdx.x] = (i < N_NODES) ? g_cnt[i] : 0;
    __syncthreads();
#pragma unroll
    for (int s = 128; s > 0; s >>= 1) {
        if (threadIdx.x < s) sh[threadIdx.x] += sh[threadIdx.x + s];
        __syncthreads();
    }
    if (threadIdx.x == 0) g_bsum[blockIdx.x] = sh[0];
}
__global__ void k_scan2() {
    __shared__ int sh[512];
    int t = threadIdx.x;
    sh[t] = (t < NB) ? g_bsum[t] : 0;
    __syncthreads();
#pragma unroll
    for (int d = 1; d < 512; d <<= 1) {
        int v = (t >= d) ? sh[t - d] : 0;
        __syncthreads();
        sh[t] += v;
        __syncthreads();
    }
    if (t < NB) g_boff[t] = sh[t] - g_bsum[t];
    if (t == 0) g_rowptr[N_NODES] = N_EDGES;
}
__global__ void k_scan3() {
    __shared__ int sh[256];
    int t = threadIdx.x;
    int i = blockIdx.x * 256 + t;
    int v = (i < N_NODES) ? g_cnt[i] : 0;
    sh[t] = v;
    __syncthreads();
#pragma unroll
    for (int d = 1; d < 256; d <<= 1) {
        int u = (t >= d) ? sh[t - d] : 0;
        __syncthreads();
        sh[t] += u;
        __syncthreads();
    }
    if (i < N_NODES) {
        int excl = g_boff[blockIdx.x] + sh[t] - v;
        g_rowptr[i] = excl;
        g_cur[i] = excl;
    }
}
__global__ void k_fill(const int* __restrict__ ei) {
    int e = blockIdx.x * blockDim.x + threadIdx.x;
    if (e >= N_EDGES) return;
    int r = ei[e];
    int c = ei[N_EDGES + e];
    int pos = atomicAdd(&g_cur[c], 1);
    g_csr_src[pos] = r;
    g_csr_w[pos] = g_dinv[r] * g_dinv[c];
}

// convert x fp32 -> fp16
__global__ void k_xf16(const float* __restrict__ x) {
    int t = blockIdx.x * blockDim.x + threadIdx.x;
    if (t >= N_NODES * (DH / 4)) return;
    float4 v = ((const float4*)x)[t];
    __half2 h0 = __floats2half2_rn(v.x, v.y);
    __half2 h1 = __floats2half2_rn(v.z, v.w);
    uint2 u;
    u.x = *(uint32_t*)&h0;
    u.y = *(uint32_t*)&h1;
    ((uint2*)g_xf16)[t] = u;
}

// ---------------- pull gather: LDG.128, split-warp edge pairing ----------------
// warp per node. lanes 0-15 = edge slot 0, lanes 16-31 = edge slot 1.
// lane handles 8 fp16 cols (sub*8 .. sub*8+7) via one uint4 load per edge.
__device__ __forceinline__ void acc8(float* acc, uint4 u, float wgt) {
    const __half2* h = (const __half2*)&u;
#pragma unroll
    for (int i = 0; i < 4; i++) {
        float2 f = __half22float2(h[i]);
        acc[2 * i]     += f.x * wgt;
        acc[2 * i + 1] += f.y * wgt;
    }
}

__device__ __forceinline__ void gather_body(const __half* __restrict__ src) {
    int w = (blockIdx.x * blockDim.x + threadIdx.x) >> 5;
    if (w >= N_NODES) return;
    int lane = threadIdx.x & 31;
    int hf  = lane >> 4;        // which edge of the pair
    int sub = lane & 15;        // column group
    const uint4* rows = (const uint4*)src;   // row r: rows[r*16 + sub]
    int s = g_rowptr[w];
    int e = g_rowptr[w + 1];

    float acc[8];
    if (hf == 0) {
        uint4 u = __ldg(&rows[(size_t)w * 16 + sub]);
        float d2 = g_dinv2[w];
        const __half2* h = (const __half2*)&u;
#pragma unroll
        for (int i = 0; i < 4; i++) {
            float2 f = __half22float2(h[i]);
            acc[2 * i]     = f.x * d2;
            acc[2 * i + 1] = f.y * d2;
        }
    } else {
#pragma unroll
        for (int k = 0; k < 8; k++) acc[k] = 0.f;
    }

    for (int base = s; base < e; base += 32) {
        int cnt = e - base;
        if (cnt > 32) cnt = 32;
        int idx = 0;
        float wt = 0.f;
        if (lane < cnt) {
            idx = g_csr_src[base + lane];
            wt = g_csr_w[base + lane];
        }
        int j = 0;
        for (; j + 4 <= cnt; j += 4) {
            int r0   = __shfl_sync(0xffffffffu, idx, j + hf);
            int r1   = __shfl_sync(0xffffffffu, idx, j + 2 + hf);
            float w0 = __shfl_sync(0xffffffffu, wt, j + hf);
            float w1 = __shfl_sync(0xffffffffu, wt, j + 2 + hf);
            uint4 a = __ldg(&rows[(size_t)r0 * 16 + sub]);
            uint4 b = __ldg(&rows[(size_t)r1 * 16 + sub]);
            acc8(acc, a, w0);
            acc8(acc, b, w1);
        }
        if (j + 2 <= cnt) {
            int r0   = __shfl_sync(0xffffffffu, idx, j + hf);
            float w0 = __shfl_sync(0xffffffffu, wt, j + hf);
            uint4 a = __ldg(&rows[(size_t)r0 * 16 + sub]);
            acc8(acc, a, w0);
            j += 2;
        }
        if (j < cnt) {   // single leftover edge: half 0 only
            int r0   = __shfl_sync(0xffffffffu, idx, j);
            float w0 = __shfl_sync(0xffffffffu, wt, j);
            if (hf == 0) {
                uint4 a = __ldg(&rows[(size_t)r0 * 16 + sub]);
                acc8(acc, a, w0);
            }
        }
    }

    // combine the two edge slots
#pragma unroll
    for (int k = 0; k < 8; k++) acc[k] += __shfl_down_sync(0xffffffffu, acc[k], 16);

    if (hf == 0) {
        float* dst = &g_agg[(size_t)w * DH + sub * 8];
        *(float4*)dst       = make_float4(acc[0], acc[1], acc[2], acc[3]);
        *(float4*)(dst + 4) = make_float4(acc[4], acc[5], acc[6], acc[7]);
    }
}
__global__ void k_gather_x16() { gather_body(g_xf16); }
__global__ void k_gather_h16() { gather_body(g_hf16); }

// ================= HMMA GEMM: h = tanh(agg @ W + b) =================
#define TSTRIDE 136            // bf16 elems per row (+8 pad)
#define TILE_BYTES (128 * TSTRIDE * 2)   // 34816
#define OFF_AH 0
#define OFF_AL (OFF_AH + TILE_BYTES)
#define OFF_BH (OFF_AL + TILE_BYTES)
#define OFF_BL (OFF_BH + TILE_BYTES)
#define GEMM_SMEM (4 * TILE_BYTES)       // 139264 bytes

__device__ __forceinline__ void split_store8(char* sm_hi, char* sm_lo,
                                             int row, int k, const float* v) {
    uint32_t hw[4], lw[4];
#pragma unroll
    for (int i = 0; i < 4; i++) {
        __nv_bfloat16 h0 = __float2bfloat16(v[2 * i]);
        __nv_bfloat16 h1 = __float2bfloat16(v[2 * i + 1]);
        float r0 = v[2 * i] - __bfloat162float(h0);
        float r1 = v[2 * i + 1] - __bfloat162float(h1);
        __nv_bfloat16 l0 = __float2bfloat16(r0);
        __nv_bfloat16 l1 = __float2bfloat16(r1);
        hw[i] = (uint32_t)__bfloat16_as_ushort(h0) | ((uint32_t)__bfloat16_as_ushort(h1) << 16);
        lw[i] = (uint32_t)__bfloat16_as_ushort(l0) | ((uint32_t)__bfloat16_as_ushort(l1) << 16);
    }
    uint32_t o = (uint32_t)row * (TSTRIDE * 2) + (uint32_t)k * 2;
    *(uint4*)(sm_hi + o) = make_uint4(hw[0], hw[1], hw[2], hw[3]);
    *(uint4*)(sm_lo + o) = make_uint4(lw[0], lw[1], lw[2], lw[3]);
}

__device__ __forceinline__ void mma_bf16(float* c, uint32_t a0, uint32_t a1,
                                         uint32_t a2, uint32_t a3,
                                         uint32_t b0, uint32_t b1) {
    asm volatile(
        "mma.sync.aligned.m16n8k16.row.col.f32.bf16.bf16.f32 "
        "{%0,%1,%2,%3}, {%4,%5,%6,%7}, {%8,%9}, {%0,%1,%2,%3};"
        : "+f"(c[0]), "+f"(c[1]), "+f"(c[2]), "+f"(c[3])
        : "r"(a0), "r"(a1), "r"(a2), "r"(a3), "r"(b0), "r"(b1));
}

// outMode: 0 -> write fp16 only (hidden layers); 1 -> write fp32 only (last layer)
__global__ void __launch_bounds__(256) k_gemm_mma(const float* __restrict__ W,
                                                  const float* __restrict__ bv,
                                                  int outMode) {
    extern __shared__ char smem[];
    int tid = threadIdx.x;
    int wid = tid >> 5;
    int lane = tid & 31;
    int rowBase = blockIdx.x * 128;

    // ---- stage A (agg) -> sAh/sAl
    {
        int r = tid >> 1;
        int kbase = (tid & 1) * 64;
        int gr = rowBase + r;
        bool valid = gr < N_NODES;
        const float* arow = &g_agg[(size_t)gr * DH];
#pragma unroll
        for (int kc = 0; kc < 64; kc += 8) {
            int k = kbase + kc;
            float v[8];
            if (valid) {
                float4 p = *(const float4*)&arow[k];
                float4 q = *(const float4*)&arow[k + 4];
                v[0] = p.x; v[1] = p.y; v[2] = p.z; v[3] = p.w;
                v[4] = q.x; v[5] = q.y; v[6] = q.z; v[7] = q.w;
            } else {
#pragma unroll
                for (int i = 0; i < 8; i++) v[i] = 0.f;
            }
            split_store8(smem + OFF_AH, smem + OFF_AL, r, k, v);
        }
    }
    // ---- stage B = W^T -> sBh/sBl  (sB[n][k] = W[k][n])
    {
        int n = tid & 127;
        int kh = (tid >> 7) * 64;
#pragma unroll
        for (int kc = 0; kc < 64; kc += 8) {
            int k = kh + kc;
            float v[8];
#pragma unroll
            for (int i = 0; i < 8; i++) v[i] = __ldg(&W[(size_t)(k + i) * DH + n]);
            split_store8(smem + OFF_BH, smem + OFF_BL, n, k, v);
        }
    }
    __syncthreads();

    // ---- compute: warp wid owns rows [wid*16, wid*16+16), all 128 cols
    int g = lane >> 2;
    int tq = lane & 3;
    float acc[16][4];
#pragma unroll
    for (int nt = 0; nt < 16; nt++) {
        acc[nt][0] = acc[nt][1] = acc[nt][2] = acc[nt][3] = 0.f;
    }

    uint32_t aoff0 = (uint32_t)(wid * 16 + g) * (TSTRIDE * 2) + tq * 4;
    uint32_t aoff1 = aoff0 + 8 * (TSTRIDE * 2);
    uint32_t boffBase = (uint32_t)g * (TSTRIDE * 2) + tq * 4;

#pragma unroll
    for (int pass = 0; pass < 3; pass++) {
        const char* pA = smem + ((pass == 2) ? OFF_AL : OFF_AH);
        const char* pB = smem + ((pass == 1) ? OFF_BL : OFF_BH);
#pragma unroll
        for (int ks = 0; ks < 8; ks++) {
            uint32_t ko = (uint32_t)ks * 32;
            uint32_t a0 = *(const uint32_t*)(pA + aoff0 + ko);
            uint32_t a2 = *(const uint32_t*)(pA + aoff0 + ko + 16);
            uint32_t a1 = *(const uint32_t*)(pA + aoff1 + ko);
            uint32_t a3 = *(const uint32_t*)(pA + aoff1 + ko + 16);
#pragma unroll
            for (int nt = 0; nt < 16; nt++) {
                uint32_t bo = boffBase + (uint32_t)nt * 8 * (TSTRIDE * 2) + ko;
                uint32_t b0 = *(const uint32_t*)(pB + bo);
                uint32_t b1 = *(const uint32_t*)(pB + bo + 16);
                mma_bf16(acc[nt], a0, a1, a2, a3, b0, b1);
            }
        }
    }

    // ---- epilogue: bias + tanh
    int row0 = rowBase + wid * 16 + g;
    int row1 = row0 + 8;
#pragma unroll
    for (int nt = 0; nt < 16; nt++) {
        int col = nt * 8 + tq * 2;
        float bx = __ldg(&bv[col]);
        float by = __ldg(&bv[col + 1]);
        if (row0 < N_NODES) {
            float ox = tanhf(acc[nt][0] + bx);
            float oy = tanhf(acc[nt][1] + by);
            if (outMode == 0) {
                *(__half2*)&g_hf16[(size_t)row0 * DH + col] = __floats2half2_rn(ox, oy);
            } else {
                *(float2*)&g_h[(size_t)row0 * DH + col] = make_float2(ox, oy);
            }
        }
        if (row1 < N_NODES) {
            float ox = tanhf(acc[nt][2] + bx);
            float oy = tanhf(acc[nt][3] + by);
            if (outMode == 0) {
                *(__half2*)&g_hf16[(size_t)row1 * DH + col] = __floats2half2_rn(ox, oy);
            } else {
                *(float2*)&g_h[(size_t)row1 * DH + col] = make_float2(ox, oy);
            }
        }
    }
}

// ---------------- pooling + linear head ----------------
__device__ __forceinline__ int lb_search(const int* b, int n, int v) {
    int lo = 0, hi = n;
    while (lo < hi) {
        int m = (lo + hi) >> 1;
        if (b[m] < v) lo = m + 1; else hi = m;
    }
    return lo;
}

__global__ void k_pool(const int* __restrict__ batch,
                       const float* __restrict__ Wl,
                       const float* __restrict__ bl,
                       float* __restrict__ out) {
    int g = blockIdx.x;
    int tid = threadIdx.x;
    int start = lb_search(batch, N_NODES, g);
    int end   = lb_search(batch, N_NODES, g + 1);
    float mx = -3.402823466e+38f;
    float sm = 0.f;
    for (int n = start; n < end; n++) {
        float v = g_h[(size_t)n * DH + tid];
        mx = fmaxf(mx, v);
        sm += v;
    }
    int cnt = end - start;
    float mn;
    if (cnt > 0) {
        mn = sm / (float)cnt;
    } else {
        mx = 0.f;
        mn = 0.f;
    }
    float contrib = mx * Wl[tid] + mn * Wl[DH + tid];
    __shared__ float red[128];
    red[tid] = contrib;
    __syncthreads();
#pragma unroll
    for (int s = 64; s > 0; s >>= 1) {
        if (tid < s) red[tid] += red[tid + s];
        __syncthreads();
    }
    if (tid == 0) out[g] = red[0] + bl[0];
}

// ---------------- launch ----------------
extern "C" void kernel_launch(void* const* d_in, const int* in_sizes, int n_in,
                              void* d_out, int out_size) {
    const float* x     = (const float*)d_in[0];
    const int*   ei    = (const int*)d_in[1];
    const int*   batch = (const int*)d_in[2];
    const float* W1 = (const float*)d_in[3];
    const float* b1 = (const float*)d_in[4];
    const float* W2 = (const float*)d_in[5];
    const float* b2 = (const float*)d_in[6];
    const float* W3 = (const float*)d_in[7];
    const float* b3 = (const float*)d_in[8];
    const float* W4 = (const float*)d_in[9];
    const float* b4 = (const float*)d_in[10];
    const float* Wl = (const float*)d_in[11];
    const float* bl = (const float*)d_in[12];
    float* out = (float*)d_out;

    cudaFuncSetAttribute(k_gemm_mma, cudaFuncAttributeMaxDynamicSharedMemorySize, GEMM_SMEM);

    const int T = 256;
    k_zero<<<(N_NODES + T - 1) / T, T>>>();
    k_deg<<<(N_EDGES + T - 1) / T, T>>>(ei);
    k_dinv<<<(N_NODES + T - 1) / T, T>>>();
    k_scan1<<<NB, 256>>>();
    k_scan2<<<1, 512>>>();
    k_scan3<<<NB, 256>>>();
    k_fill<<<(N_EDGES + T - 1) / T, T>>>(ei);
    k_xf16<<<(N_NODES * (DH / 4) + T - 1) / T, T>>>(x);

    const int gatherBlocks = (N_NODES * 32 + T - 1) / T;
    const int gemmBlocks = (N_NODES + 127) / 128;

    k_gather_x16<<<gatherBlocks, T>>>();
    k_gemm_mma<<<gemmBlocks, 256, GEMM_SMEM>>>(W1, b1, 0);
    k_gather_h16<<<gatherBlocks, T>>>();
    k_gemm_mma<<<gemmBlocks, 256, GEMM_SMEM>>>(W2, b2, 0);
    k_gather_h16<<<gatherBlocks, T>>>();
    k_gemm_mma<<<gemmBlocks, 256, GEMM_SMEM>>>(W3, b3, 0);
    k_gather_h16<<<gatherBlocks, T>>>();
    k_gemm_mma<<<gemmBlocks, 256, GEMM_SMEM>>>(W4, b4, 1);

    k_pool<<<NGRAPH, 128>>>(batch, Wl, bl, out);
}